// round 14
// baseline (speedup 1.0000x reference)
#include <cuda_runtime.h>
#include <cuda_bf16.h>
#include <cstdint>

// Problem constants
#define M_ROWS 4096
#define K_DIM  256
#define NN     16384
#define KTOP   1638
#define KE     768                  // 3 x 256 (bf16 hi/lo split expansion)
#define NKT    48                   // KE/16 k16-tiles
#define SLOTS  64                   // CSC capacity per column (max nnz ~48)

// ---------------------------------------------------------------------------
// Scratch
//   g_A: A operand pre-permuted into m16n8k16 A-fragment order:
//        [mtile(256)][kt(48)][lane(32)] x uint4 {reg0..reg3}
//   g_B: B operand in B-fragment order: [ntile(2048)][kt(48)][lane] x uint2
//   g_pairT/g_cnt: exact-fp32 CSC of W for the top-K boundary fixup.
// ---------------------------------------------------------------------------
__device__ uint4  g_A[(size_t)256 * NKT * 32];          // 6.3 MB
__device__ uint2  g_B[(size_t)2048 * NKT * 32];         // 25.2 MB
__device__ float2 g_pairT[(size_t)SLOTS * NN];          // 8.4 MB
__device__ int    g_cnt[NN];

__device__ __forceinline__ uint32_t pk_bf16(float a, float b) {
    return (uint32_t)__bfloat16_as_ushort(__float2bfloat16(a))
         | ((uint32_t)__bfloat16_as_ushort(__float2bfloat16(b)) << 16);
}
__device__ __forceinline__ float lo_part(float v) {
    return v - __bfloat162float(__float2bfloat16(v));
}

// ---------------------------------------------------------------------------
// Kernel: build exact CSC (for fixup). Coalesced over n.
// ---------------------------------------------------------------------------
__global__ void __launch_bounds__(128) build_pack_kernel(const float* __restrict__ W) {
    const int n = blockIdx.x * blockDim.x + threadIdx.x;
    if (n >= NN) return;
    int c = 0;
    for (int k = 0; k < K_DIM; ++k) {
        const float w = W[(size_t)k * NN + n];
        if (w != 0.0f) {
            if (c < SLOTS) g_pairT[(size_t)c * NN + n] = make_float2(w, __int_as_float(k));
            ++c;
        }
    }
    g_cnt[n] = (c < SLOTS) ? c : SLOTS;
}

// ---------------------------------------------------------------------------
// Kernel: prep A' (x split hi|lo|hi) directly into A-fragment order.
// m16n8k16 A frag (row-major 16x16 bf16), g=lane>>2, t=lane&3:
//   reg0={A[g][2t],A[g][2t+1]} reg1={A[g+8][2t],A[g+8][2t+1]}
//   reg2={A[g][2t+8],A[g][2t+9]} reg3={A[g+8][2t+8],A[g+8][2t+9]}
// ---------------------------------------------------------------------------
__global__ void __launch_bounds__(256) prep_a_kernel(const float* __restrict__ x) {
    const int id = blockIdx.x * 256 + threadIdx.x;      // < 256*48*32
    const int mtile = id / (NKT * 32);
    const int kt    = (id % (NKT * 32)) >> 5;
    const int lane  = id & 31;
    const int g = lane >> 2, t = lane & 3;
    const int s = kt / 16;                              // split 0,1,2
    const int kb = (kt % 16) * 16 + t * 2;              // k of first elem
    const int r0 = mtile * 16 + g, r1 = r0 + 8;

    float e[8];
#pragma unroll
    for (int q = 0; q < 8; ++q) {
        const int rr = (q & 1) ? r1 : r0;               // q: r0,r1 alternate
        const int kk = kb + ((q >> 2) ? 8 : 0) + 0;     // pairs handled below
        (void)kk; (void)rr; e[q] = 0.f;
    }
    // explicit 8 elements: (row, k) pairs
    const float v00 = x[(size_t)r0 * K_DIM + kb + 0];
    const float v01 = x[(size_t)r0 * K_DIM + kb + 1];
    const float v10 = x[(size_t)r1 * K_DIM + kb + 0];
    const float v11 = x[(size_t)r1 * K_DIM + kb + 1];
    const float v02 = x[(size_t)r0 * K_DIM + kb + 8];
    const float v03 = x[(size_t)r0 * K_DIM + kb + 9];
    const float v12 = x[(size_t)r1 * K_DIM + kb + 8];
    const float v13 = x[(size_t)r1 * K_DIM + kb + 9];

    // split s==1 -> lo(x), else hi (the raw value; pk rounds to bf16)
    const float a00 = (s == 1) ? lo_part(v00) : v00;
    const float a01 = (s == 1) ? lo_part(v01) : v01;
    const float a10 = (s == 1) ? lo_part(v10) : v10;
    const float a11 = (s == 1) ? lo_part(v11) : v11;
    const float a02 = (s == 1) ? lo_part(v02) : v02;
    const float a03 = (s == 1) ? lo_part(v03) : v03;
    const float a12 = (s == 1) ? lo_part(v12) : v12;
    const float a13 = (s == 1) ? lo_part(v13) : v13;

    g_A[id] = make_uint4(pk_bf16(a00, a01), pk_bf16(a10, a11),
                         pk_bf16(a02, a03), pk_bf16(a12, a13));
}

// ---------------------------------------------------------------------------
// Kernel: prep B' (W^T split hi|hi|lo) into B-fragment order.
// m16n8k16 B frag (k16 x n8, .col => stored [n][k]):
//   reg0={B[2t][g],B[2t+1][g]}  reg1={B[2t+8][g],B[2t+9][g]}   (k idx, n=g)
// ---------------------------------------------------------------------------
__global__ void __launch_bounds__(256) prep_b_kernel(const float* __restrict__ W) {
    const int id = blockIdx.x * 256 + threadIdx.x;      // < 2048*48*32
    const int ntile = id / (NKT * 32);
    const int kt    = (id % (NKT * 32)) >> 5;
    const int lane  = id & 31;
    const int g = lane >> 2, t = lane & 3;
    const int s = kt / 16;
    const int kb = (kt % 16) * 16 + t * 2;
    const int n = ntile * 8 + g;

    const float w0 = W[(size_t)(kb + 0) * NN + n];
    const float w1 = W[(size_t)(kb + 1) * NN + n];
    const float w2 = W[(size_t)(kb + 8) * NN + n];
    const float w3 = W[(size_t)(kb + 9) * NN + n];
    const float b0 = (s == 2) ? lo_part(w0) : w0;
    const float b1 = (s == 2) ? lo_part(w1) : w1;
    const float b2 = (s == 2) ? lo_part(w2) : w2;
    const float b3 = (s == 2) ? lo_part(w3) : w3;

    g_B[id] = make_uint2(pk_bf16(b0, b1), pk_bf16(b2, b3));
}

// ---------------------------------------------------------------------------
// Kernel: tensor-core GEMM  out = relu(A' @ B'^T + bias)  (h~, err ~1.5e-6)
// CTA tile 128x128, 256 threads / 8 warps (2m x 4n), warp tile 64x32.
// K=768 in 12 chunks of 64, double-buffered smem staging of frag blocks.
// ---------------------------------------------------------------------------
#define GT 256
#define GSMEM (2 * 32768)

__global__ void __launch_bounds__(GT, 2) gemm_mma_kernel(
    const float* __restrict__ bias, float* __restrict__ out)
{
    extern __shared__ char smem[];
    const int tid  = threadIdx.x;
    const int warp = tid >> 5, lane = tid & 31;
    const int wm = warp >> 2, wn = warp & 3;            // 2 x 4
    const int nb = blockIdx.x, mb = blockIdx.y;
    const int row0 = mb * 128, col0 = nb * 128;

    float acc[4][4][4];
#pragma unroll
    for (int i = 0; i < 4; ++i)
#pragma unroll
        for (int j = 0; j < 4; ++j)
#pragma unroll
            for (int q = 0; q < 4; ++q) acc[i][j][q] = 0.f;

    auto As = [&](int p) { return (uint4*)(smem + p * 32768); };
    auto Bs = [&](int p) { return (uint2*)(smem + p * 32768 + 16384); };

    auto copy_chunk = [&](int c, int p) {
        uint4* a = As(p); uint2* b = Bs(p);
        for (int u = tid; u < 1024; u += GT) {          // A: 8 mt x 4 kt x 32
            const int mt = u >> 7, r = (u >> 5) & 3, ln = u & 31;
            a[u] = g_A[((size_t)(mb * 8 + mt) * NKT + c * 4 + r) * 32 + ln];
        }
        for (int u = tid; u < 2048; u += GT) {          // B: 16 nt x 4 kt x 32
            const int nt = u >> 7, r = (u >> 5) & 3, ln = u & 31;
            b[u] = g_B[((size_t)(nb * 16 + nt) * NKT + c * 4 + r) * 32 + ln];
        }
    };

    copy_chunk(0, 0);
    __syncthreads();

    for (int c = 0; c < 12; ++c) {
        const int p = c & 1;
        if (c + 1 < 12) copy_chunk(c + 1, p ^ 1);
        const uint4* a = As(p); const uint2* b = Bs(p);
#pragma unroll
        for (int kt4 = 0; kt4 < 4; ++kt4) {
            uint4 af[4]; uint2 bf[4];
#pragma unroll
            for (int i = 0; i < 4; ++i)
                af[i] = a[((wm * 4 + i) * 4 + kt4) * 32 + lane];
#pragma unroll
            for (int j = 0; j < 4; ++j)
                bf[j] = b[((wn * 4 + j) * 4 + kt4) * 32 + lane];
#pragma unroll
            for (int i = 0; i < 4; ++i)
#pragma unroll
                for (int j = 0; j < 4; ++j) {
                    asm volatile(
                        "mma.sync.aligned.m16n8k16.row.col.f32.bf16.bf16.f32 "
                        "{%0,%1,%2,%3}, {%4,%5,%6,%7}, {%8,%9}, {%0,%1,%2,%3};\n"
                        : "+f"(acc[i][j][0]), "+f"(acc[i][j][1]),
                          "+f"(acc[i][j][2]), "+f"(acc[i][j][3])
                        : "r"(af[i].x), "r"(af[i].y), "r"(af[i].z), "r"(af[i].w),
                          "r"(bf[j].x), "r"(bf[j].y));
                }
        }
        __syncthreads();
    }

    // epilogue: bias + relu, direct STG.64 (32B sectors per row group)
    const int g = lane >> 2, t = lane & 3;
#pragma unroll
    for (int i = 0; i < 4; ++i)
#pragma unroll
        for (int j = 0; j < 4; ++j) {
            const int row = row0 + (wm * 4 + i) * 16 + g;
            const int col = col0 + (wn * 4 + j) * 8 + t * 2;
            const float b0 = __ldg(bias + col), b1 = __ldg(bias + col + 1);
            float2 v0, v1;
            v0.x = fmaxf(acc[i][j][0] + b0, 0.f);
            v0.y = fmaxf(acc[i][j][1] + b1, 0.f);
            v1.x = fmaxf(acc[i][j][2] + b0, 0.f);
            v1.y = fmaxf(acc[i][j][3] + b1, 0.f);
            *(float2*)(out + (size_t)row * NN + col) = v0;
            *(float2*)(out + (size_t)(row + 8) * NN + col) = v1;
        }
}

// ---------------------------------------------------------------------------
// Kernel: top-K with EXACT boundary fixup.
// h~ has ~1.5e-6 abs error; bin width ~3e-3 >> error. Histogram h~ (12-bit),
// find threshold bin; elements in higher bins are kept with huge margin;
// elements in the threshold bin are recomputed EXACTLY from the CSC (same
// k-ascending fmaf order as the prior rel_err=0.0 kernels), ranked exactly
// (lowest-index ties, matching lax.top_k), and scattered with exact values.
// ---------------------------------------------------------------------------
#define CAP 1024

__global__ void __launch_bounds__(256) topk_kernel(
    float* __restrict__ out, const float* __restrict__ x,
    const float* __restrict__ bias)
{
    __shared__ int hist[4096];
    __shared__ unsigned int candv[CAP];
    __shared__ int candi[CAP];
    __shared__ int keepf[CAP];
    __shared__ float xrow[K_DIM];
    __shared__ int chunksum[256];
    __shared__ int s_b1, s_krem, s_cnt;

    const int t = threadIdx.x;
    const int lane = t & 31;
    const int row = blockIdx.x;
    float* rp = out + (size_t)row * NN;
    const uint4* rp4 = (const uint4*)rp;

    xrow[t] = x[(size_t)row * K_DIM + t];               // 256 threads = K_DIM
    for (int i = t; i < 4096; i += 256) hist[i] = 0;
    if (t == 0) s_cnt = 0;
    __syncthreads();

    // ---- pass 1: 12-bit histogram of h~ bits ----
    {
        int zc = 0;
        for (int i = t; i < NN / 4; i += 256) {
            const uint4 q = rp4[i];
            if (q.x) atomicAdd(&hist[q.x >> 20], 1); else ++zc;
            if (q.y) atomicAdd(&hist[q.y >> 20], 1); else ++zc;
            if (q.z) atomicAdd(&hist[q.z >> 20], 1); else ++zc;
            if (q.w) atomicAdd(&hist[q.w >> 20], 1); else ++zc;
        }
#pragma unroll
        for (int off = 16; off; off >>= 1) zc += __shfl_down_sync(0xffffffffu, zc, off);
        if (lane == 0 && zc) atomicAdd(&hist[0], zc);
    }
    __syncthreads();
    { int s = 0; for (int k = 0; k < 16; ++k) s += hist[t * 16 + k]; chunksum[t] = s; }
    __syncthreads();
    if (t == 0) {
        int kr = KTOP, c = 255;
        for (;; --c) { const int h = chunksum[c]; if (h >= kr) break; kr -= h; }
        int b = c * 16 + 15;
        for (;; --b) { const int h = hist[b]; if (h >= kr) break; kr -= h; }
        s_b1 = b; s_krem = kr;
    }
    __syncthreads();
    const int b1 = s_b1;
    const int krem = s_krem;

    if (b1 == 0) {
        // threshold in the tiny/zero bin: keep all positives (diff ~1e-32)
        for (int i = t; i < NN / 4; i += 256) {
            uint4 q = rp4[i];
            // positives kept as-is; zeros stay zero
            ((uint4*)rp)[i] = q;
        }
        return;
    }

    // ---- pass 2: compact threshold-bin candidates ----
    for (int i = t; i < NN / 4; i += 256) {
        const uint4 q = rp4[i];
        const int base = i * 4;
        if ((int)(q.x >> 20) == b1) { const int p = atomicAdd(&s_cnt, 1); if (p < CAP) { candv[p] = q.x; candi[p] = base + 0; } }
        if ((int)(q.y >> 20) == b1) { const int p = atomicAdd(&s_cnt, 1); if (p < CAP) { candv[p] = q.y; candi[p] = base + 1; } }
        if ((int)(q.z >> 20) == b1) { const int p = atomicAdd(&s_cnt, 1); if (p < CAP) { candv[p] = q.z; candi[p] = base + 2; } }
        if ((int)(q.w >> 20) == b1) { const int p = atomicAdd(&s_cnt, 1); if (p < CAP) { candv[p] = q.w; candi[p] = base + 3; } }
    }
    __syncthreads();
    const int cnt = s_cnt;

    if (cnt > CAP) {
        // practically unreachable fallback: keep the whole bin (h~ values)
        const unsigned int tb = ((unsigned int)b1 << 20);
        for (int i = t; i < NN / 4; i += 256) {
            uint4 q = rp4[i];
            unsigned int* pc = (unsigned int*)&q;
#pragma unroll
            for (int c2 = 0; c2 < 4; ++c2) if (pc[c2] < tb) pc[c2] = 0u;
            ((uint4*)rp)[i] = q;
        }
        return;
    }

    // ---- exact recompute of candidates (k-ascending fmaf, as ref-matched) ----
    for (int i = t; i < cnt; i += 256) {
        const int n = candi[i];
        const int cn = g_cnt[n];
        float sum = 0.f;
        for (int s = 0; s < cn; ++s) {
            const float2 p = g_pairT[(size_t)s * NN + n];
            sum = fmaf(xrow[__float_as_int(p.y)], p.x, sum);
        }
        const float h = fmaxf(sum + __ldg(bias + n), 0.f);
        candv[i] = __float_as_uint(h);
    }
    __syncthreads();

    // ---- exact ranking among candidates, lowest-index ties first ----
    for (int i = t; i < cnt; i += 256) {
        const unsigned int u = candv[i];
        const int idx = candi[i];
        int r = 0;
        for (int j = 0; j < cnt; ++j) {
            const unsigned int v = candv[j];
            r += (v > u) || (v == u && candi[j] < idx);
        }
        keepf[i] = (r < krem);
    }
    __syncthreads();

    // ---- write pass: higher bins keep h~, threshold bin zeroed ----
    for (int i = t; i < NN / 4; i += 256) {
        uint4 q = rp4[i];
        unsigned int* pc = (unsigned int*)&q;
#pragma unroll
        for (int c2 = 0; c2 < 4; ++c2) {
            const int bin = (int)(pc[c2] >> 20);
            if (bin <= b1) pc[c2] = 0u;
        }
        ((uint4*)rp)[i] = q;
    }
    __syncthreads();

    // ---- scatter kept candidates with EXACT values ----
    for (int i = t; i < cnt; i += 256)
        if (keepf[i]) rp[candi[i]] = __uint_as_float(candv[i]);
}

// ---------------------------------------------------------------------------
// Launch
// ---------------------------------------------------------------------------
extern "C" void kernel_launch(void* const* d_in, const int* in_sizes, int n_in,
                              void* d_out, int out_size)
{
    const float* x = nullptr;
    const float* W = nullptr;
    const float* bias = nullptr;
    for (int i = 0; i < n_in; ++i) {
        if (in_sizes[i] == M_ROWS * K_DIM)      x = (const float*)d_in[i];
        else if (in_sizes[i] == K_DIM * NN)     W = (const float*)d_in[i];
        else if (in_sizes[i] == NN)             bias = (const float*)d_in[i];
    }
    float* out = (float*)d_out;

    cudaFuncSetAttribute(gemm_mma_kernel, cudaFuncAttributeMaxDynamicSharedMemorySize, GSMEM);

    build_pack_kernel<<<NN / 128, 128>>>(W);
    prep_a_kernel<<<(256 * NKT * 32) / 256, 256>>>(x);
    prep_b_kernel<<<(2048 * NKT * 32) / 256, 256>>>(W);

    dim3 ggrid(NN / 128, M_ROWS / 128);       // 128 x 32
    gemm_mma_kernel<<<ggrid, GT, GSMEM>>>(bias, out);

    topk_kernel<<<M_ROWS, 256>>>(out, x, bias);
}

// round 15
// speedup vs baseline: 1.1114x; 1.1114x over previous
#include <cuda_runtime.h>
#include <cuda_bf16.h>
#include <cstdint>

// Problem constants
#define M_ROWS 4096
#define K_DIM  256
#define NN     16384
#define KTOP   1638
#define KE     768                  // 3 x 256 (bf16 hi/lo split expansion)
#define NKT    48                   // KE/16 k16-tiles
#define SLOTS  64                   // CSC capacity per column (max nnz ~48)

// ---------------------------------------------------------------------------
// Scratch
//   g_A: A operand in m16n8k16 A-fragment order: [mtile(256)][kt(48)][lane]x uint4
//   g_B: B operand in B-fragment order: [ntile(2048)][kt(48)][lane] x uint2
//   g_pairT/g_cnt: exact-fp32 CSC of W for the top-K boundary fixup.
// ---------------------------------------------------------------------------
__device__ uint4  g_A[(size_t)256 * NKT * 32];          // 6.3 MB
__device__ uint2  g_B[(size_t)2048 * NKT * 32];         // 25.2 MB
__device__ float2 g_pairT[(size_t)SLOTS * NN];          // 8.4 MB
__device__ int    g_cnt[NN];

__device__ __forceinline__ uint32_t pk_bf16(float a, float b) {
    return (uint32_t)__bfloat16_as_ushort(__float2bfloat16(a))
         | ((uint32_t)__bfloat16_as_ushort(__float2bfloat16(b)) << 16);
}
__device__ __forceinline__ float lo_part(float v) {
    return v - __bfloat162float(__float2bfloat16(v));
}
__device__ __forceinline__ uint32_t smem_u32(const void* p) {
    uint32_t a;
    asm("{ .reg .u64 t; cvta.to.shared.u64 t, %1; cvt.u32.u64 %0, t; }" : "=r"(a) : "l"(p));
    return a;
}
#define CP_ASYNC16(dst, src) \
    asm volatile("cp.async.ca.shared.global [%0], [%1], 16;\n" :: "r"(dst), "l"(src))
#define CP_COMMIT() asm volatile("cp.async.commit_group;\n")
#define CP_WAIT1()  asm volatile("cp.async.wait_group 1;\n" ::: "memory")

// ---------------------------------------------------------------------------
// Kernel: build exact CSC (for fixup). Coalesced over n.
// ---------------------------------------------------------------------------
__global__ void __launch_bounds__(128) build_pack_kernel(const float* __restrict__ W) {
    const int n = blockIdx.x * blockDim.x + threadIdx.x;
    if (n >= NN) return;
    int c = 0;
    for (int k = 0; k < K_DIM; ++k) {
        const float w = W[(size_t)k * NN + n];
        if (w != 0.0f) {
            if (c < SLOTS) g_pairT[(size_t)c * NN + n] = make_float2(w, __int_as_float(k));
            ++c;
        }
    }
    g_cnt[n] = (c < SLOTS) ? c : SLOTS;
}

// ---------------------------------------------------------------------------
// Kernel: prep A' (x split hi|lo|hi) directly into A-fragment order.
// A frag (16x16 bf16 row-major), g=lane>>2, t=lane&3:
//   reg0={A[g][2t],A[g][2t+1]} reg1={A[g+8][...]} reg2=+8cols reg3=both
// ---------------------------------------------------------------------------
__global__ void __launch_bounds__(256) prep_a_kernel(const float* __restrict__ x) {
    const int id = blockIdx.x * 256 + threadIdx.x;      // < 256*48*32
    const int mtile = id / (NKT * 32);
    const int kt    = (id % (NKT * 32)) >> 5;
    const int lane  = id & 31;
    const int g = lane >> 2, t = lane & 3;
    const int s = kt / 16;                              // split 0,1,2
    const int kb = (kt % 16) * 16 + t * 2;
    const int r0 = mtile * 16 + g, r1 = r0 + 8;

    const float v00 = x[(size_t)r0 * K_DIM + kb + 0];
    const float v01 = x[(size_t)r0 * K_DIM + kb + 1];
    const float v10 = x[(size_t)r1 * K_DIM + kb + 0];
    const float v11 = x[(size_t)r1 * K_DIM + kb + 1];
    const float v02 = x[(size_t)r0 * K_DIM + kb + 8];
    const float v03 = x[(size_t)r0 * K_DIM + kb + 9];
    const float v12 = x[(size_t)r1 * K_DIM + kb + 8];
    const float v13 = x[(size_t)r1 * K_DIM + kb + 9];

    const float a00 = (s == 1) ? lo_part(v00) : v00;
    const float a01 = (s == 1) ? lo_part(v01) : v01;
    const float a10 = (s == 1) ? lo_part(v10) : v10;
    const float a11 = (s == 1) ? lo_part(v11) : v11;
    const float a02 = (s == 1) ? lo_part(v02) : v02;
    const float a03 = (s == 1) ? lo_part(v03) : v03;
    const float a12 = (s == 1) ? lo_part(v12) : v12;
    const float a13 = (s == 1) ? lo_part(v13) : v13;

    g_A[id] = make_uint4(pk_bf16(a00, a01), pk_bf16(a10, a11),
                         pk_bf16(a02, a03), pk_bf16(a12, a13));
}

// ---------------------------------------------------------------------------
// Kernel: prep B' (W^T split hi|hi|lo) into B-fragment order, via a 64x64
// smem transpose tile so the W reads are COALESCED (R14 read at 64KB stride).
// B frag: reg0={B[2t][g],B[2t+1][g]} reg1={B[2t+8][g],B[2t+9][g]} (k, n=g).
// ---------------------------------------------------------------------------
__global__ void __launch_bounds__(256) prep_b_kernel(const float* __restrict__ W) {
    __shared__ float tw[64][65];
    const int n0 = blockIdx.x * 64;                     // 256 blocks
    const int k0 = blockIdx.y * 64;                     // 4 blocks
    const int tid = threadIdx.x;

    // coalesced load: 64 rows x 64 cols
    for (int u = tid; u < 64 * 64; u += 256) {
        const int kk = u >> 6, nn = u & 63;
        tw[kk][nn] = W[(size_t)(k0 + kk) * NN + n0 + nn];
    }
    __syncthreads();

    // emit fragment words: 8 ntiles x 4 local k16-tiles x 32 lanes, 3 splits
    for (int u = tid; u < 8 * 4 * 32; u += 256) {
        const int nt  = u >> 7;                          // 0..7
        const int ktl = (u >> 5) & 3;                    // 0..3
        const int ln  = u & 31;
        const int g = ln >> 2, t = ln & 3;
        const int nn = nt * 8 + g;                       // local col
        const int kb = ktl * 16 + t * 2;                 // local k
        const float w0 = tw[kb + 0][nn];
        const float w1 = tw[kb + 1][nn];
        const float w2 = tw[kb + 8][nn];
        const float w3 = tw[kb + 9][nn];
        const int ntile = (n0 >> 3) + nt;
#pragma unroll
        for (int s = 0; s < 3; ++s) {
            const int ktg = s * 16 + (k0 >> 4) + ktl;
            const float b0 = (s == 2) ? lo_part(w0) : w0;
            const float b1 = (s == 2) ? lo_part(w1) : w1;
            const float b2 = (s == 2) ? lo_part(w2) : w2;
            const float b3 = (s == 2) ? lo_part(w3) : w3;
            g_B[((size_t)ntile * NKT + ktg) * 32 + ln] =
                make_uint2(pk_bf16(b0, b1), pk_bf16(b2, b3));
        }
    }
}

// ---------------------------------------------------------------------------
// Kernel: tensor-core GEMM  out = relu(A' @ B'^T + bias)  (h~, err ~1.5e-6)
// CTA tile 128x128, 256 threads / 8 warps (2m x 4n), warp tile 64x32.
// K=768 in 12 chunks of 64; 3-stage cp.async pipeline (32KB/stage).
// Epilogue staged through smem for coalesced float4 DRAM writes.
// ---------------------------------------------------------------------------
#define GT 256
#define STAGE_B 32768
#define GSMEM (3 * STAGE_B)          // 96KB -> 2 CTAs/SM
#define OS_STRIDE 129

__global__ void __launch_bounds__(GT, 2) gemm_mma_kernel(
    const float* __restrict__ bias, float* __restrict__ out)
{
    extern __shared__ char smem[];
    const uint32_t sbase = smem_u32(smem);
    const int tid  = threadIdx.x;
    const int warp = tid >> 5, lane = tid & 31;
    const int wm = warp >> 2, wn = warp & 3;            // 2 x 4
    const int nb = blockIdx.x, mb = blockIdx.y;
    const int row0 = mb * 128, col0 = nb * 128;

    float acc[4][4][4];
#pragma unroll
    for (int i = 0; i < 4; ++i)
#pragma unroll
        for (int j = 0; j < 4; ++j)
#pragma unroll
            for (int q = 0; q < 4; ++q) acc[i][j][q] = 0.f;

    const uint4* gA4 = g_A;
    const uint4* gB4 = (const uint4*)g_B;

    // async-copy chunk c into stage p. A: 1024 uint4; B: 1024 uint4.
    auto issue_copy = [&](int c, int p) {
        const uint32_t abase = sbase + p * STAGE_B;
        const uint32_t bbase = abase + 16384;
#pragma unroll
        for (int u4 = 0; u4 < 4; ++u4) {
            const int u = tid + u4 * GT;                 // 0..1023
            // A: mt = u>>7, within = u&127 (r*32+ln contiguous)
            const uint4* srcA = gA4 + ((size_t)(mb * 8 + (u >> 7)) * NKT + c * 4) * 32 + (u & 127);
            CP_ASYNC16(abase + u * 16, srcA);
            // B: nt = u>>6, within = u&63 uint4 (128 uint2 contiguous)
            const uint4* srcB = gB4 + ((size_t)(nb * 16 + (u >> 6)) * NKT + c * 4) * 16 + (u & 63);
            CP_ASYNC16(bbase + u * 16, srcB);
        }
        CP_COMMIT();
    };

    issue_copy(0, 0);
    issue_copy(1, 1);

    for (int c = 0; c < 12; ++c) {
        CP_WAIT1();                                      // chunk c resident
        __syncthreads();                                 // all warps see it; prev mma done
        if (c + 2 < 12) issue_copy(c + 2, (c + 2) % 3);
        else CP_COMMIT();                                // keep group count uniform

        const int p = c % 3;
        const uint4* a = (const uint4*)(smem + p * STAGE_B);
        const uint2* b = (const uint2*)(smem + p * STAGE_B + 16384);
#pragma unroll
        for (int kt4 = 0; kt4 < 4; ++kt4) {
            uint4 af[4]; uint2 bf[4];
#pragma unroll
            for (int i = 0; i < 4; ++i)
                af[i] = a[((wm * 4 + i) * 4 + kt4) * 32 + lane];
#pragma unroll
            for (int j = 0; j < 4; ++j)
                bf[j] = b[((wn * 4 + j) * 4 + kt4) * 32 + lane];
#pragma unroll
            for (int i = 0; i < 4; ++i)
#pragma unroll
                for (int j = 0; j < 4; ++j) {
                    asm volatile(
                        "mma.sync.aligned.m16n8k16.row.col.f32.bf16.bf16.f32 "
                        "{%0,%1,%2,%3}, {%4,%5,%6,%7}, {%8,%9}, {%0,%1,%2,%3};\n"
                        : "+f"(acc[i][j][0]), "+f"(acc[i][j][1]),
                          "+f"(acc[i][j][2]), "+f"(acc[i][j][3])
                        : "r"(af[i].x), "r"(af[i].y), "r"(af[i].z), "r"(af[i].w),
                          "r"(bf[j].x), "r"(bf[j].y));
                }
        }
    }
    __syncthreads();                                     // smem free for epilogue

    // epilogue: bias + relu -> smem [128][129] -> coalesced float4 flush
    float* os = (float*)smem;
    const int g = lane >> 2, t = lane & 3;
#pragma unroll
    for (int i = 0; i < 4; ++i)
#pragma unroll
        for (int j = 0; j < 4; ++j) {
            const int rl = (wm * 4 + i) * 16 + g;
            const int cl = (wn * 4 + j) * 8 + t * 2;
            const float b0 = __ldg(bias + col0 + cl), b1 = __ldg(bias + col0 + cl + 1);
            os[(rl + 0) * OS_STRIDE + cl + 0] = fmaxf(acc[i][j][0] + b0, 0.f);
            os[(rl + 0) * OS_STRIDE + cl + 1] = fmaxf(acc[i][j][1] + b1, 0.f);
            os[(rl + 8) * OS_STRIDE + cl + 0] = fmaxf(acc[i][j][2] + b0, 0.f);
            os[(rl + 8) * OS_STRIDE + cl + 1] = fmaxf(acc[i][j][3] + b1, 0.f);
        }
    __syncthreads();
    for (int l = tid; l < 128 * 32; l += GT) {
        const int r = l >> 5, c4 = (l & 31) * 4;
        float4 v;
        v.x = os[r * OS_STRIDE + c4 + 0];
        v.y = os[r * OS_STRIDE + c4 + 1];
        v.z = os[r * OS_STRIDE + c4 + 2];
        v.w = os[r * OS_STRIDE + c4 + 3];
        *(float4*)(out + (size_t)(row0 + r) * NN + col0 + c4) = v;
    }
}

// ---------------------------------------------------------------------------
// Kernel: top-K with EXACT boundary fixup (validated R14, rel_err 2.8e-6).
// 12-bit histogram of h~; higher bins kept (margin >> 1.5e-6 error);
// threshold-bin candidates recomputed EXACTLY from the CSC, ranked exactly
// (lowest-index ties, matching lax.top_k), scattered with exact values.
// ---------------------------------------------------------------------------
#define CAP 1024

__global__ void __launch_bounds__(256) topk_kernel(
    float* __restrict__ out, const float* __restrict__ x,
    const float* __restrict__ bias)
{
    __shared__ int hist[4096];
    __shared__ unsigned int candv[CAP];
    __shared__ int candi[CAP];
    __shared__ int keepf[CAP];
    __shared__ float xrow[K_DIM];
    __shared__ int chunksum[256];
    __shared__ int s_b1, s_krem, s_cnt;

    const int t = threadIdx.x;
    const int lane = t & 31;
    const int row = blockIdx.x;
    float* rp = out + (size_t)row * NN;
    const uint4* rp4 = (const uint4*)rp;

    xrow[t] = x[(size_t)row * K_DIM + t];
    for (int i = t; i < 4096; i += 256) hist[i] = 0;
    if (t == 0) s_cnt = 0;
    __syncthreads();

    // ---- pass 1: 12-bit histogram of h~ bits ----
    {
        int zc = 0;
        for (int i = t; i < NN / 4; i += 256) {
            const uint4 q = rp4[i];
            if (q.x) atomicAdd(&hist[q.x >> 20], 1); else ++zc;
            if (q.y) atomicAdd(&hist[q.y >> 20], 1); else ++zc;
            if (q.z) atomicAdd(&hist[q.z >> 20], 1); else ++zc;
            if (q.w) atomicAdd(&hist[q.w >> 20], 1); else ++zc;
        }
#pragma unroll
        for (int off = 16; off; off >>= 1) zc += __shfl_down_sync(0xffffffffu, zc, off);
        if (lane == 0 && zc) atomicAdd(&hist[0], zc);
    }
    __syncthreads();
    { int s = 0; for (int k = 0; k < 16; ++k) s += hist[t * 16 + k]; chunksum[t] = s; }
    __syncthreads();
    if (t == 0) {
        int kr = KTOP, c = 255;
        for (;; --c) { const int h = chunksum[c]; if (h >= kr) break; kr -= h; }
        int b = c * 16 + 15;
        for (;; --b) { const int h = hist[b]; if (h >= kr) break; kr -= h; }
        s_b1 = b; s_krem = kr;
    }
    __syncthreads();
    const int b1 = s_b1;
    const int krem = s_krem;

    if (b1 == 0) return;   // threshold in zero/denormal bin: keep everything

    // ---- pass 2: compact threshold-bin candidates ----
    for (int i = t; i < NN / 4; i += 256) {
        const uint4 q = rp4[i];
        const int base = i * 4;
        if ((int)(q.x >> 20) == b1) { const int p = atomicAdd(&s_cnt, 1); if (p < CAP) { candv[p] = q.x; candi[p] = base + 0; } }
        if ((int)(q.y >> 20) == b1) { const int p = atomicAdd(&s_cnt, 1); if (p < CAP) { candv[p] = q.y; candi[p] = base + 1; } }
        if ((int)(q.z >> 20) == b1) { const int p = atomicAdd(&s_cnt, 1); if (p < CAP) { candv[p] = q.z; candi[p] = base + 2; } }
        if ((int)(q.w >> 20) == b1) { const int p = atomicAdd(&s_cnt, 1); if (p < CAP) { candv[p] = q.w; candi[p] = base + 3; } }
    }
    __syncthreads();
    const int cnt = s_cnt;

    if (cnt > CAP) {
        // practically unreachable fallback: keep the whole bin (h~ values)
        const unsigned int tb = ((unsigned int)b1 << 20);
        for (int i = t; i < NN / 4; i += 256) {
            uint4 q = rp4[i];
            unsigned int* pc = (unsigned int*)&q;
#pragma unroll
            for (int c2 = 0; c2 < 4; ++c2) if (pc[c2] < tb) pc[c2] = 0u;
            ((uint4*)rp)[i] = q;
        }
        return;
    }

    // ---- exact recompute of candidates (k-ascending fmaf, ref-matched) ----
    for (int i = t; i < cnt; i += 256) {
        const int n = candi[i];
        const int cn = g_cnt[n];
        float sum = 0.f;
        for (int s = 0; s < cn; ++s) {
            const float2 p = g_pairT[(size_t)s * NN + n];
            sum = fmaf(xrow[__float_as_int(p.y)], p.x, sum);
        }
        const float h = fmaxf(sum + __ldg(bias + n), 0.f);
        candv[i] = __float_as_uint(h);
    }
    __syncthreads();

    // ---- exact ranking among candidates, lowest-index ties first ----
    for (int i = t; i < cnt; i += 256) {
        const unsigned int u = candv[i];
        const int idx = candi[i];
        int r = 0;
        for (int j = 0; j < cnt; ++j) {
            const unsigned int v = candv[j];
            r += (v > u) || (v == u && candi[j] < idx);
        }
        keepf[i] = (r < krem);
    }
    __syncthreads();

    // ---- write pass: higher bins keep h~, threshold bin & below zeroed ----
    for (int i = t; i < NN / 4; i += 256) {
        uint4 q = rp4[i];
        unsigned int* pc = (unsigned int*)&q;
#pragma unroll
        for (int c2 = 0; c2 < 4; ++c2)
            if ((int)(pc[c2] >> 20) <= b1) pc[c2] = 0u;
        ((uint4*)rp)[i] = q;
    }
    __syncthreads();

    // ---- scatter kept candidates with EXACT values ----
    for (int i = t; i < cnt; i += 256)
        if (keepf[i]) rp[candi[i]] = __uint_as_float(candv[i]);
}

// ---------------------------------------------------------------------------
// Launch
// ---------------------------------------------------------------------------
extern "C" void kernel_launch(void* const* d_in, const int* in_sizes, int n_in,
                              void* d_out, int out_size)
{
    const float* x = nullptr;
    const float* W = nullptr;
    const float* bias = nullptr;
    for (int i = 0; i < n_in; ++i) {
        if (in_sizes[i] == M_ROWS * K_DIM)      x = (const float*)d_in[i];
        else if (in_sizes[i] == K_DIM * NN)     W = (const float*)d_in[i];
        else if (in_sizes[i] == NN)             bias = (const float*)d_in[i];
    }
    float* out = (float*)d_out;

    cudaFuncSetAttribute(gemm_mma_kernel, cudaFuncAttributeMaxDynamicSharedMemorySize, GSMEM);

    build_pack_kernel<<<NN / 128, 128>>>(W);
    prep_a_kernel<<<(256 * NKT * 32) / 256, 256>>>(x);
    {
        dim3 g(NN / 64, K_DIM / 64);     // 256 x 4
        prep_b_kernel<<<g, 256>>>(W);
    }

    dim3 ggrid(NN / 128, M_ROWS / 128);  // 128 x 32
    gemm_mma_kernel<<<ggrid, GT, GSMEM>>>(bias, out);

    topk_kernel<<<M_ROWS, 256>>>(out, x, bias);
}